// round 14
// baseline (speedup 1.0000x reference)
#include <cuda_runtime.h>
#include <cuda_bf16.h>
#include <cstdint>

#define N_NODES 50000
#define N_EDGES 800000
#define IN_DIM  128
#define HID     128
#define OUT_DIM 64
#define CAP     96            // max in-degree (Poisson λ=16 → P(>96) ~ 0)

#define NCHUNK     4
#define CHUNK_T    196                    // tiles per chunk (64 nodes/tile)
#define CHUNK_N    (CHUNK_T * 64)         // 12544 nodes per chunk

// Scratch (device globals — no allocations allowed)
__device__ int   g_idx64;
__device__ int   g_cur[N_NODES];
__device__ float g_dinv[N_NODES];
__device__ float g_agg[(size_t)N_NODES * IN_DIM];
__device__ int   g_src[(size_t)N_NODES * CAP];

// Host-side stream/event resources, created once at load (before any harness
// mem checkpoint; events are DisableTiming => graph-capture legal).
static cudaStream_t g_s2;
static cudaEvent_t  g_evg[NCHUNK];
static cudaEvent_t  g_evj;
namespace {
struct ResInit {
    ResInit() {
        cudaStreamCreateWithFlags(&g_s2, cudaStreamNonBlocking);
        for (int i = 0; i < NCHUNK; i++)
            cudaEventCreateWithFlags(&g_evg[i], cudaEventDisableTiming);
        cudaEventCreateWithFlags(&g_evj, cudaEventDisableTiming);
    }
};
static ResInit g_res_init;
}

__device__ __forceinline__ int edge_idx(const void* ei, int i) {
    if (g_idx64) return (int)((const long long*)ei)[i];
    return ((const int*)ei)[i];
}

// ---------------------------------------------------------------------------
// k0: zero cursors + dtype detection
// ---------------------------------------------------------------------------
__global__ void k_init(const void* __restrict__ ei) {
    int i = blockIdx.x * blockDim.x + threadIdx.x;
    if (i < N_NODES) g_cur[i] = 0;
    if (blockIdx.x == 0) {
        __shared__ int s_ok;
        if (threadIdx.x == 0) s_ok = 1;
        __syncthreads();
        long long v = ((const long long*)ei)[threadIdx.x];  // 2KB, in-bounds either way
        if (v < 0 || v >= N_NODES) atomicAnd(&s_ok, 0);
        __syncthreads();
        if (threadIdx.x == 0) g_idx64 = s_ok;
    }
}

// k1: combined count + bucket fill
__global__ void k_fill(const void* __restrict__ ei) {
    int e = blockIdx.x * blockDim.x + threadIdx.x;
    if (e < N_EDGES) {
        int r = edge_idx(ei, e);
        int c = edge_idx(ei, N_EDGES + e);
        int p = atomicAdd(&g_cur[c], 1);
        if (p < CAP) g_src[(size_t)c * CAP + p] = r;
    }
}

// k2: dinv = rsqrt(deg+1)
__global__ void k_dinv() {
    int i = blockIdx.x * blockDim.x + threadIdx.x;
    if (i < N_NODES) g_dinv[i] = rsqrtf((float)(g_cur[i] + 1));
}

// ---------------------------------------------------------------------------
// k3: gather for one node chunk (warp per node; proven R11 loop)
// ---------------------------------------------------------------------------
__global__ void __launch_bounds__(256) k_gather(const float* __restrict__ h, int base) {
    int node = base + ((blockIdx.x * blockDim.x + threadIdx.x) >> 5);
    if (node >= N_NODES || node >= base + CHUNK_N) return;
    int tx = threadIdx.x & 31;
    const float4* h4 = (const float4*)h;

    float dn = __ldg(g_dinv + node);
    float4 acc = __ldg(h4 + (size_t)node * 32 + tx);
    acc.x *= dn; acc.y *= dn; acc.z *= dn; acc.w *= dn;   // self term

    int cnt = __ldg(g_cur + node);
    if (cnt > CAP) cnt = CAP;
    const int* src = g_src + (size_t)node * CAP;
    int p = 0;
    for (; p + 4 <= cnt; p += 4) {
        int r0 = __ldg(src + p + 0), r1 = __ldg(src + p + 1);
        int r2 = __ldg(src + p + 2), r3 = __ldg(src + p + 3);
        float d0 = __ldg(g_dinv + r0), d1 = __ldg(g_dinv + r1);
        float d2 = __ldg(g_dinv + r2), d3 = __ldg(g_dinv + r3);
        float4 v0 = __ldg(h4 + (size_t)r0 * 32 + tx);
        float4 v1 = __ldg(h4 + (size_t)r1 * 32 + tx);
        float4 v2 = __ldg(h4 + (size_t)r2 * 32 + tx);
        float4 v3 = __ldg(h4 + (size_t)r3 * 32 + tx);
        acc.x += v0.x * d0 + v1.x * d1 + v2.x * d2 + v3.x * d3;
        acc.y += v0.y * d0 + v1.y * d1 + v2.y * d2 + v3.y * d3;
        acc.z += v0.z * d0 + v1.z * d1 + v2.z * d2 + v3.z * d3;
        acc.w += v0.w * d0 + v1.w * d1 + v2.w * d2 + v3.w * d3;
    }
    for (; p < cnt; p++) {
        int r = __ldg(src + p);
        float d = __ldg(g_dinv + r);
        float4 v = __ldg(h4 + (size_t)r * 32 + tx);
        acc.x += v.x * d; acc.y += v.y * d; acc.z += v.z * d; acc.w += v.w * d;
    }
    acc.x *= dn; acc.y *= dn; acc.z *= dn; acc.w *= dn;
    ((float4*)g_agg)[(size_t)node * 32 + tx] = acc;
}

// ---------------------------------------------------------------------------
// k4: scalar MLP for one tile chunk (proven R2/R11 code)
// ---------------------------------------------------------------------------
__global__ void __launch_bounds__(256) k_mlp(const float* __restrict__ Wg,
                                             const float* __restrict__ bg,
                                             const float* __restrict__ Wf,
                                             const float* __restrict__ bf,
                                             float* __restrict__ out,
                                             int tile0) {
    __shared__ float sA[64 * 128];

    int node0 = (tile0 + blockIdx.x) * 64;
    if (node0 >= N_NODES) return;       // uniform per block, before any sync
    int tid = threadIdx.x;
    int tx = tid & 31;
    int ty = tid >> 5;

    for (int i = tid; i < 64 * 32; i += 256) {
        int node = node0 + (i >> 5);
        float4 v = make_float4(0.f, 0.f, 0.f, 0.f);
        if (node < N_NODES) v = ((const float4*)g_agg)[(size_t)node * 32 + (i & 31)];
        ((float4*)sA)[i] = v;
    }
    __syncthreads();

    // ---- phase 1: hid = A @ Wg + bg ----
    float acc[8][4];
    {
        float4 b = __ldg((const float4*)bg + tx);
        #pragma unroll
        for (int i = 0; i < 8; i++) {
            acc[i][0] = b.x; acc[i][1] = b.y; acc[i][2] = b.z; acc[i][3] = b.w;
        }
    }
    #pragma unroll 4
    for (int k = 0; k < 128; k++) {
        float4 w = __ldg((const float4*)(Wg + k * 128) + tx);
        #pragma unroll
        for (int i = 0; i < 8; i++) {
            float a = sA[(8 * ty + i) * 128 + k];
            acc[i][0] += a * w.x;
            acc[i][1] += a * w.y;
            acc[i][2] += a * w.z;
            acc[i][3] += a * w.w;
        }
    }
    __syncthreads();

    #pragma unroll
    for (int i = 0; i < 8; i++) {
        float4 v;
        v.x = fmaxf(acc[i][0], 0.f);
        v.y = fmaxf(acc[i][1], 0.f);
        v.z = fmaxf(acc[i][2], 0.f);
        v.w = fmaxf(acc[i][3], 0.f);
        ((float4*)sA)[(8 * ty + i) * 32 + tx] = v;
    }
    __syncthreads();

    // ---- phase 2: out = hid @ Wf + bf ----
    float o[8][2];
    {
        float2 b = __ldg((const float2*)bf + tx);
        #pragma unroll
        for (int i = 0; i < 8; i++) { o[i][0] = b.x; o[i][1] = b.y; }
    }
    #pragma unroll 4
    for (int k = 0; k < 128; k++) {
        float2 w = __ldg((const float2*)(Wf + k * 64) + tx);
        #pragma unroll
        for (int i = 0; i < 8; i++) {
            float a = sA[(8 * ty + i) * 128 + k];
            o[i][0] += a * w.x;
            o[i][1] += a * w.y;
        }
    }

    #pragma unroll
    for (int i = 0; i < 8; i++) {
        int node = node0 + 8 * ty + i;
        if (node < N_NODES) {
            float2 v; v.x = o[i][0]; v.y = o[i][1];
            ((float2*)out)[(size_t)node * 32 + tx] = v;
        }
    }
}

// ---------------------------------------------------------------------------
// launch — chunked gather/MLP pipeline across two captured streams.
// inputs: h[f32 N*128], edge_index[2*E int32-or-int64], W_gcn, b_gcn, W_fc, b_fc
// output: f32 N*64
// ---------------------------------------------------------------------------
extern "C" void kernel_launch(void* const* d_in, const int* in_sizes, int n_in,
                              void* d_out, int out_size) {
    const float* h  = (const float*)d_in[0];
    const void*  ei = d_in[1];
    const float* Wg = (const float*)d_in[2];
    const float* bg = (const float*)d_in[3];
    const float* Wf = (const float*)d_in[4];
    const float* bf = (const float*)d_in[5];
    float* out = (float*)d_out;

    k_init<<<(N_NODES + 255) / 256, 256>>>(ei);
    k_fill<<<(N_EDGES + 255) / 256, 256>>>(ei);
    k_dinv<<<(N_NODES + 255) / 256, 256>>>();

    const int GATHER_BLOCKS = CHUNK_N / 8;   // warp per node, 8 warps/block
    for (int c = 0; c < NCHUNK; c++) {
        int base = c * CHUNK_N;
        k_gather<<<GATHER_BLOCKS, 256>>>(h, base);
        cudaEventRecord(g_evg[c], 0);
        cudaStreamWaitEvent(g_s2, g_evg[c], 0);
        k_mlp<<<CHUNK_T, 256, 0, g_s2>>>(Wg, bg, Wf, bf, out, c * CHUNK_T);
    }
    // join side stream back into the capture origin stream
    cudaEventRecord(g_evj, g_s2);
    cudaStreamWaitEvent(0, g_evj, 0);
}

// round 15
// speedup vs baseline: 1.3145x; 1.3145x over previous
#include <cuda_runtime.h>
#include <cuda_fp16.h>
#include <cuda_bf16.h>
#include <cstdint>

#define N_NODES 50000
#define N_EDGES 800000
#define IN_DIM  128
#define HID     128
#define OUT_DIM 64
#define CAP     96          // max in-degree (Poisson λ=16 → P(>96) ~ 0)

// Scratch (device globals — no allocations allowed)
__device__ int   g_idx64;                          // 1 if edge_index is int64
__device__ int   g_cur[N_NODES];                   // cursor == in-degree after fill
__device__ float g_dinv[N_NODES];
__device__ uint2 g_hs16[(size_t)N_NODES * 32];     // fp16(h*dinv): 4 halves per uint2 (12.8 MB)
__device__ float g_agg[(size_t)N_NODES * IN_DIM];  // aggregated features (fp32)
__device__ int   g_src[(size_t)N_NODES * CAP];     // bucketed source lists (19.2 MB)

__device__ __forceinline__ int edge_idx(const void* ei, int i) {
    if (g_idx64) return (int)((const long long*)ei)[i];
    return ((const int*)ei)[i];
}

// ---------------------------------------------------------------------------
// k0: zero cursors + dtype detection (JAX silently downcasts int64 -> int32)
// ---------------------------------------------------------------------------
__global__ void k_init(const void* __restrict__ ei) {
    int i = blockIdx.x * blockDim.x + threadIdx.x;
    if (i < N_NODES) g_cur[i] = 0;
    if (blockIdx.x == 0) {
        __shared__ int s_ok;
        if (threadIdx.x == 0) s_ok = 1;
        __syncthreads();
        long long v = ((const long long*)ei)[threadIdx.x];  // 2KB, in-bounds either way
        if (v < 0 || v >= N_NODES) atomicAnd(&s_ok, 0);
        __syncthreads();
        if (threadIdx.x == 0) g_idx64 = s_ok;
    }
}

// k1: combined count + bucket fill (cursor doubles as in-degree histogram)
__global__ void k_fill(const void* __restrict__ ei) {
    int e = blockIdx.x * blockDim.x + threadIdx.x;
    if (e < N_EDGES) {
        int r = edge_idx(ei, e);
        int c = edge_idx(ei, N_EDGES + e);
        int p = atomicAdd(&g_cur[c], 1);
        if (p < CAP) g_src[(size_t)c * CAP + p] = r;
    }
}

// k2: dinv = rsqrt(deg+1)
__global__ void k_dinv() {
    int i = blockIdx.x * blockDim.x + threadIdx.x;
    if (i < N_NODES) g_dinv[i] = rsqrtf((float)(g_cur[i] + 1));
}

// k3: hs16[n][k] = fp16(h[n][k] * dinv[n])  — halves gather LTS traffic
__global__ void k_hs16(const float* __restrict__ h) {
    int idx = blockIdx.x * blockDim.x + threadIdx.x;     // over N*32 float4 groups
    if (idx >= N_NODES * 32) return;
    float dn = __ldg(g_dinv + (idx >> 5));
    float4 v = __ldg((const float4*)h + idx);
    __half2 a = __floats2half2_rn(v.x * dn, v.y * dn);
    __half2 b = __floats2half2_rn(v.z * dn, v.w * dn);
    uint2 o;
    o.x = *(const uint32_t*)&a;
    o.y = *(const uint32_t*)&b;
    g_hs16[idx] = o;
}

// ---------------------------------------------------------------------------
// k4: gather (warp per node): agg[n] = dinv[n] * (hs16[n] + sum_in hs16[r])
//   lane = 4 features (one uint2 = 4 halves); fp32 accumulation;
//   src indices loaded as int4 (16B-aligned: CAP*4 = 384 ≡ 0 mod 16).
// ---------------------------------------------------------------------------
__global__ void __launch_bounds__(256) k_gather() {
    int node = (blockIdx.x * blockDim.x + threadIdx.x) >> 5;
    if (node >= N_NODES) return;
    int tx = threadIdx.x & 31;

    // self term
    uint2 s = __ldg(g_hs16 + (size_t)node * 32 + tx);
    float2 s0 = __half22float2(*(const __half2*)&s.x);
    float2 s1 = __half22float2(*(const __half2*)&s.y);
    float4 acc = make_float4(s0.x, s0.y, s1.x, s1.y);

    int cnt = __ldg(g_cur + node);
    if (cnt > CAP) cnt = CAP;
    const int* src = g_src + (size_t)node * CAP;
    int p = 0;
    for (; p + 4 <= cnt; p += 4) {
        int4 rr = __ldg((const int4*)(src + p));
        uint2 v0 = __ldg(g_hs16 + (size_t)rr.x * 32 + tx);
        uint2 v1 = __ldg(g_hs16 + (size_t)rr.y * 32 + tx);
        uint2 v2 = __ldg(g_hs16 + (size_t)rr.z * 32 + tx);
        uint2 v3 = __ldg(g_hs16 + (size_t)rr.w * 32 + tx);
        float2 a0 = __half22float2(*(const __half2*)&v0.x);
        float2 b0 = __half22float2(*(const __half2*)&v0.y);
        float2 a1 = __half22float2(*(const __half2*)&v1.x);
        float2 b1 = __half22float2(*(const __half2*)&v1.y);
        float2 a2 = __half22float2(*(const __half2*)&v2.x);
        float2 b2 = __half22float2(*(const __half2*)&v2.y);
        float2 a3 = __half22float2(*(const __half2*)&v3.x);
        float2 b3 = __half22float2(*(const __half2*)&v3.y);
        acc.x += a0.x + a1.x + a2.x + a3.x;
        acc.y += a0.y + a1.y + a2.y + a3.y;
        acc.z += b0.x + b1.x + b2.x + b3.x;
        acc.w += b0.y + b1.y + b2.y + b3.y;
    }
    for (; p < cnt; p++) {
        int r = __ldg(src + p);
        uint2 v = __ldg(g_hs16 + (size_t)r * 32 + tx);
        float2 a = __half22float2(*(const __half2*)&v.x);
        float2 b = __half22float2(*(const __half2*)&v.y);
        acc.x += a.x; acc.y += a.y; acc.z += b.x; acc.w += b.y;
    }
    float dn = __ldg(g_dinv + node);
    acc.x *= dn; acc.y *= dn; acc.z *= dn; acc.w *= dn;
    ((float4*)g_agg)[(size_t)node * 32 + tx] = acc;
}

// ---------------------------------------------------------------------------
// k5: scalar MLP (proven R2/R11 code): out = relu(agg@Wg+bg)@Wf + bf
//   64 nodes/block, 256 threads; natural register allocation.
// ---------------------------------------------------------------------------
__global__ void __launch_bounds__(256) k_mlp(const float* __restrict__ Wg,
                                             const float* __restrict__ bg,
                                             const float* __restrict__ Wf,
                                             const float* __restrict__ bf,
                                             float* __restrict__ out) {
    __shared__ float sA[64 * 128];

    int tid = threadIdx.x;
    int tx = tid & 31;
    int ty = tid >> 5;
    int node0 = blockIdx.x * 64;

    for (int i = tid; i < 64 * 32; i += 256) {
        int node = node0 + (i >> 5);
        float4 v = make_float4(0.f, 0.f, 0.f, 0.f);
        if (node < N_NODES) v = __ldg((const float4*)g_agg + (size_t)node * 32 + (i & 31));
        ((float4*)sA)[i] = v;
    }
    __syncthreads();

    // ---- phase 1: hid = A @ Wg + bg ----
    float acc[8][4];
    {
        float4 b = __ldg((const float4*)bg + tx);
        #pragma unroll
        for (int i = 0; i < 8; i++) {
            acc[i][0] = b.x; acc[i][1] = b.y; acc[i][2] = b.z; acc[i][3] = b.w;
        }
    }
    #pragma unroll 4
    for (int k = 0; k < 128; k++) {
        float4 w = __ldg((const float4*)(Wg + k * 128) + tx);
        #pragma unroll
        for (int i = 0; i < 8; i++) {
            float a = sA[(8 * ty + i) * 128 + k];
            acc[i][0] += a * w.x;
            acc[i][1] += a * w.y;
            acc[i][2] += a * w.z;
            acc[i][3] += a * w.w;
        }
    }
    __syncthreads();

    #pragma unroll
    for (int i = 0; i < 8; i++) {
        float4 v;
        v.x = fmaxf(acc[i][0], 0.f);
        v.y = fmaxf(acc[i][1], 0.f);
        v.z = fmaxf(acc[i][2], 0.f);
        v.w = fmaxf(acc[i][3], 0.f);
        ((float4*)sA)[(8 * ty + i) * 32 + tx] = v;
    }
    __syncthreads();

    // ---- phase 2: out = hid @ Wf + bf ----
    float o[8][2];
    {
        float2 b = __ldg((const float2*)bf + tx);
        #pragma unroll
        for (int i = 0; i < 8; i++) { o[i][0] = b.x; o[i][1] = b.y; }
    }
    #pragma unroll 4
    for (int k = 0; k < 128; k++) {
        float2 w = __ldg((const float2*)(Wf + k * 64) + tx);
        #pragma unroll
        for (int i = 0; i < 8; i++) {
            float a = sA[(8 * ty + i) * 128 + k];
            o[i][0] += a * w.x;
            o[i][1] += a * w.y;
        }
    }

    #pragma unroll
    for (int i = 0; i < 8; i++) {
        int node = node0 + 8 * ty + i;
        if (node < N_NODES) {
            float2 v; v.x = o[i][0]; v.y = o[i][1];
            ((float2*)out)[(size_t)node * 32 + tx] = v;
        }
    }
}

// ---------------------------------------------------------------------------
// launch — inputs: h[f32 N*128], edge_index[2*E int32-or-int64],
//          W_gcn[f32 128*128], b_gcn[f32 128], W_fc[f32 128*64], b_fc[f32 64]
// output: f32 N*64
// ---------------------------------------------------------------------------
extern "C" void kernel_launch(void* const* d_in, const int* in_sizes, int n_in,
                              void* d_out, int out_size) {
    const float* h  = (const float*)d_in[0];
    const void*  ei = d_in[1];
    const float* Wg = (const float*)d_in[2];
    const float* bg = (const float*)d_in[3];
    const float* Wf = (const float*)d_in[4];
    const float* bf = (const float*)d_in[5];
    float* out = (float*)d_out;

    k_init  <<<(N_NODES + 255) / 256, 256>>>(ei);
    k_fill  <<<(N_EDGES + 255) / 256, 256>>>(ei);
    k_dinv  <<<(N_NODES + 255) / 256, 256>>>();
    k_hs16  <<<(N_NODES * 32 + 255) / 256, 256>>>(h);
    k_gather<<<(N_NODES * 32 + 255) / 256, 256>>>();      // warp per node
    k_mlp   <<<(N_NODES + 63) / 64, 256>>>(Wg, bg, Wf, bf, out);
}

// round 16
// speedup vs baseline: 1.3370x; 1.0171x over previous
#include <cuda_runtime.h>
#include <cuda_fp16.h>
#include <cuda_bf16.h>
#include <cstdint>

#define N_NODES 50000
#define N_EDGES 800000
#define IN_DIM  128
#define HID     128
#define OUT_DIM 64
#define CAP     96          // max in-degree (Poisson λ=16 → P(>96) ~ 0)

// Scratch (device globals — no allocations allowed)
__device__ int   g_idx64;                          // 1 if edge_index is int64
__device__ int   g_cur[N_NODES];                   // cursor == in-degree after fill
__device__ float g_dinv[N_NODES];
__device__ uint2 g_hs16[(size_t)N_NODES * 32];     // fp16(h*dinv): 4 halves per uint2 (12.8 MB)
__device__ float g_agg[(size_t)N_NODES * IN_DIM];  // aggregated features (fp32)
__device__ int   g_src[(size_t)N_NODES * CAP];     // bucketed source lists (19.2 MB)

__device__ __forceinline__ int edge_idx(const void* ei, int i) {
    if (g_idx64) return (int)((const long long*)ei)[i];
    return ((const int*)ei)[i];
}

// ---------------------------------------------------------------------------
// k0: zero cursors + dtype detection (JAX silently downcasts int64 -> int32)
// ---------------------------------------------------------------------------
__global__ void k_init(const void* __restrict__ ei) {
    int i = blockIdx.x * blockDim.x + threadIdx.x;
    if (i < N_NODES) g_cur[i] = 0;
    if (blockIdx.x == 0) {
        __shared__ int s_ok;
        if (threadIdx.x == 0) s_ok = 1;
        __syncthreads();
        long long v = ((const long long*)ei)[threadIdx.x];  // 2KB, in-bounds either way
        if (v < 0 || v >= N_NODES) atomicAnd(&s_ok, 0);
        __syncthreads();
        if (threadIdx.x == 0) g_idx64 = s_ok;
    }
}

// k1: combined count + bucket fill (cursor doubles as in-degree histogram)
__global__ void k_fill(const void* __restrict__ ei) {
    int e = blockIdx.x * blockDim.x + threadIdx.x;
    if (e < N_EDGES) {
        int r = edge_idx(ei, e);
        int c = edge_idx(ei, N_EDGES + e);
        int p = atomicAdd(&g_cur[c], 1);
        if (p < CAP) g_src[(size_t)c * CAP + p] = r;
    }
}

// ---------------------------------------------------------------------------
// k2: fused dinv + fp16 payload:  dn = rsqrt(deg+1) computed per thread from
//     g_cur (free ALU in a DRAM-bound kernel); hs16 = fp16(h * dn);
//     lane 0 of each node also stores g_dinv for the gather's final scale.
// ---------------------------------------------------------------------------
__global__ void k_hs16(const float* __restrict__ h) {
    int idx = blockIdx.x * blockDim.x + threadIdx.x;     // over N*32 float4 groups
    if (idx >= N_NODES * 32) return;
    int node = idx >> 5;
    float dn = rsqrtf((float)(__ldg(g_cur + node) + 1)); // +1 self-loop
    if ((idx & 31) == 0) g_dinv[node] = dn;
    float4 v = __ldg((const float4*)h + idx);
    __half2 a = __floats2half2_rn(v.x * dn, v.y * dn);
    __half2 b = __floats2half2_rn(v.z * dn, v.w * dn);
    uint2 o;
    o.x = *(const uint32_t*)&a;
    o.y = *(const uint32_t*)&b;
    g_hs16[idx] = o;
}

// ---------------------------------------------------------------------------
// k3: gather (warp per node): agg[n] = dinv[n] * (hs16[n] + sum_in hs16[r])
//   lane = 4 features (one uint2 = 4 halves); fp32 accumulation;
//   src indices loaded as int4 (16B-aligned: CAP*4 = 384 ≡ 0 mod 16).
// ---------------------------------------------------------------------------
__global__ void __launch_bounds__(256) k_gather() {
    int node = (blockIdx.x * blockDim.x + threadIdx.x) >> 5;
    if (node >= N_NODES) return;
    int tx = threadIdx.x & 31;

    // self term
    uint2 s = __ldg(g_hs16 + (size_t)node * 32 + tx);
    float2 s0 = __half22float2(*(const __half2*)&s.x);
    float2 s1 = __half22float2(*(const __half2*)&s.y);
    float4 acc = make_float4(s0.x, s0.y, s1.x, s1.y);

    int cnt = __ldg(g_cur + node);
    if (cnt > CAP) cnt = CAP;
    const int* src = g_src + (size_t)node * CAP;
    int p = 0;
    for (; p + 4 <= cnt; p += 4) {
        int4 rr = __ldg((const int4*)(src + p));
        uint2 v0 = __ldg(g_hs16 + (size_t)rr.x * 32 + tx);
        uint2 v1 = __ldg(g_hs16 + (size_t)rr.y * 32 + tx);
        uint2 v2 = __ldg(g_hs16 + (size_t)rr.z * 32 + tx);
        uint2 v3 = __ldg(g_hs16 + (size_t)rr.w * 32 + tx);
        float2 a0 = __half22float2(*(const __half2*)&v0.x);
        float2 b0 = __half22float2(*(const __half2*)&v0.y);
        float2 a1 = __half22float2(*(const __half2*)&v1.x);
        float2 b1 = __half22float2(*(const __half2*)&v1.y);
        float2 a2 = __half22float2(*(const __half2*)&v2.x);
        float2 b2 = __half22float2(*(const __half2*)&v2.y);
        float2 a3 = __half22float2(*(const __half2*)&v3.x);
        float2 b3 = __half22float2(*(const __half2*)&v3.y);
        acc.x += a0.x + a1.x + a2.x + a3.x;
        acc.y += a0.y + a1.y + a2.y + a3.y;
        acc.z += b0.x + b1.x + b2.x + b3.x;
        acc.w += b0.y + b1.y + b2.y + b3.y;
    }
    for (; p < cnt; p++) {
        int r = __ldg(src + p);
        uint2 v = __ldg(g_hs16 + (size_t)r * 32 + tx);
        float2 a = __half22float2(*(const __half2*)&v.x);
        float2 b = __half22float2(*(const __half2*)&v.y);
        acc.x += a.x; acc.y += a.y; acc.z += b.x; acc.w += b.y;
    }
    float dn = __ldg(g_dinv + node);
    acc.x *= dn; acc.y *= dn; acc.z *= dn; acc.w *= dn;
    ((float4*)g_agg)[(size_t)node * 32 + tx] = acc;
}

// ---------------------------------------------------------------------------
// k4: scalar MLP (proven R2/R11 code): out = relu(agg@Wg+bg)@Wf + bf
//   64 nodes/block, 256 threads; natural register allocation.
// ---------------------------------------------------------------------------
__global__ void __launch_bounds__(256) k_mlp(const float* __restrict__ Wg,
                                             const float* __restrict__ bg,
                                             const float* __restrict__ Wf,
                                             const float* __restrict__ bf,
                                             float* __restrict__ out) {
    __shared__ float sA[64 * 128];

    int tid = threadIdx.x;
    int tx = tid & 31;
    int ty = tid >> 5;
    int node0 = blockIdx.x * 64;

    for (int i = tid; i < 64 * 32; i += 256) {
        int node = node0 + (i >> 5);
        float4 v = make_float4(0.f, 0.f, 0.f, 0.f);
        if (node < N_NODES) v = __ldg((const float4*)g_agg + (size_t)node * 32 + (i & 31));
        ((float4*)sA)[i] = v;
    }
    __syncthreads();

    // ---- phase 1: hid = A @ Wg + bg ----
    float acc[8][4];
    {
        float4 b = __ldg((const float4*)bg + tx);
        #pragma unroll
        for (int i = 0; i < 8; i++) {
            acc[i][0] = b.x; acc[i][1] = b.y; acc[i][2] = b.z; acc[i][3] = b.w;
        }
    }
    #pragma unroll 4
    for (int k = 0; k < 128; k++) {
        float4 w = __ldg((const float4*)(Wg + k * 128) + tx);
        #pragma unroll
        for (int i = 0; i < 8; i++) {
            float a = sA[(8 * ty + i) * 128 + k];
            acc[i][0] += a * w.x;
            acc[i][1] += a * w.y;
            acc[i][2] += a * w.z;
            acc[i][3] += a * w.w;
        }
    }
    __syncthreads();

    #pragma unroll
    for (int i = 0; i < 8; i++) {
        float4 v;
        v.x = fmaxf(acc[i][0], 0.f);
        v.y = fmaxf(acc[i][1], 0.f);
        v.z = fmaxf(acc[i][2], 0.f);
        v.w = fmaxf(acc[i][3], 0.f);
        ((float4*)sA)[(8 * ty + i) * 32 + tx] = v;
    }
    __syncthreads();

    // ---- phase 2: out = hid @ Wf + bf ----
    float o[8][2];
    {
        float2 b = __ldg((const float2*)bf + tx);
        #pragma unroll
        for (int i = 0; i < 8; i++) { o[i][0] = b.x; o[i][1] = b.y; }
    }
    #pragma unroll 4
    for (int k = 0; k < 128; k++) {
        float2 w = __ldg((const float2*)(Wf + k * 64) + tx);
        #pragma unroll
        for (int i = 0; i < 8; i++) {
            float a = sA[(8 * ty + i) * 128 + k];
            o[i][0] += a * w.x;
            o[i][1] += a * w.y;
        }
    }

    #pragma unroll
    for (int i = 0; i < 8; i++) {
        int node = node0 + 8 * ty + i;
        if (node < N_NODES) {
            float2 v; v.x = o[i][0]; v.y = o[i][1];
            ((float2*)out)[(size_t)node * 32 + tx] = v;
        }
    }
}

// ---------------------------------------------------------------------------
// launch — inputs: h[f32 N*128], edge_index[2*E int32-or-int64],
//          W_gcn[f32 128*128], b_gcn[f32 128], W_fc[f32 128*64], b_fc[f32 64]
// output: f32 N*64
// ---------------------------------------------------------------------------
extern "C" void kernel_launch(void* const* d_in, const int* in_sizes, int n_in,
                              void* d_out, int out_size) {
    const float* h  = (const float*)d_in[0];
    const void*  ei = d_in[1];
    const float* Wg = (const float*)d_in[2];
    const float* bg = (const float*)d_in[3];
    const float* Wf = (const float*)d_in[4];
    const float* bf = (const float*)d_in[5];
    float* out = (float*)d_out;

    k_init  <<<(N_NODES + 255) / 256, 256>>>(ei);
    k_fill  <<<(N_EDGES + 255) / 256, 256>>>(ei);
    k_hs16  <<<(N_NODES * 32 + 255) / 256, 256>>>(h);   // fused dinv + fp16 payload
    k_gather<<<(N_NODES * 32 + 255) / 256, 256>>>();    // warp per node
    k_mlp   <<<(N_NODES + 63) / 64, 256>>>(Wg, bg, Wf, bf, out);
}

// round 17
// speedup vs baseline: 1.6474x; 1.2322x over previous
#include <cuda_runtime.h>
#include <cuda_fp16.h>
#include <cuda_bf16.h>
#include <cstdint>

#define N_NODES 50000
#define N_EDGES 800000
#define IN_DIM  128
#define HID     128
#define OUT_DIM 64
#define CAP     96          // max in-degree (Poisson λ=16 → P(>96) ~ 0)

// Scratch (device globals — no allocations allowed)
__device__ int     g_idx64;
__device__ int     g_cur[N_NODES];                   // cursor == in-degree after fill
__device__ float   g_dinv[N_NODES];
__device__ uint2   g_hs16[(size_t)N_NODES * 32];     // fp16(h*dinv) payload (12.8 MB)
__device__ float   g_agg[(size_t)N_NODES * IN_DIM];  // aggregated features (fp32)
__device__ int     g_src[(size_t)N_NODES * CAP];     // bucketed source lists (19.2 MB)
__device__ __half2 g_Wgh[64 * 128];                  // Wg packed [kp][c], pair over k (32 KB)
__device__ __half2 g_Wfh[64 * 64];                   // Wf packed [kp][c] (16 KB)

__device__ __forceinline__ int edge_idx(const void* ei, int i) {
    if (g_idx64) return (int)((const long long*)ei)[i];
    return ((const int*)ei)[i];
}

// ---------------------------------------------------------------------------
// k0: zero cursors + pack weights into k-paired half2 images + dtype detection
// ---------------------------------------------------------------------------
__global__ void k_init(const void* __restrict__ ei,
                       const float* __restrict__ Wg,
                       const float* __restrict__ Wf) {
    int i = blockIdx.x * blockDim.x + threadIdx.x;
    if (i < N_NODES) g_cur[i] = 0;
    if (i < 64 * 128) {                       // [kp][c] <- (Wg[2kp][c], Wg[2kp+1][c])
        int kp = i >> 7, c = i & 127;
        g_Wgh[i] = __floats2half2_rn(Wg[(2 * kp) * HID + c], Wg[(2 * kp + 1) * HID + c]);
    }
    if (i < 64 * 64) {
        int kp = i >> 6, c = i & 63;
        g_Wfh[i] = __floats2half2_rn(Wf[(2 * kp) * OUT_DIM + c], Wf[(2 * kp + 1) * OUT_DIM + c]);
    }
    if (blockIdx.x == 0) {
        __shared__ int s_ok;
        if (threadIdx.x == 0) s_ok = 1;
        __syncthreads();
        long long v = ((const long long*)ei)[threadIdx.x];  // 2KB, in-bounds either way
        if (v < 0 || v >= N_NODES) atomicAnd(&s_ok, 0);
        __syncthreads();
        if (threadIdx.x == 0) g_idx64 = s_ok;
    }
}

// k1: combined count + bucket fill
__global__ void k_fill(const void* __restrict__ ei) {
    int e = blockIdx.x * blockDim.x + threadIdx.x;
    if (e < N_EDGES) {
        int r = edge_idx(ei, e);
        int c = edge_idx(ei, N_EDGES + e);
        int p = atomicAdd(&g_cur[c], 1);
        if (p < CAP) g_src[(size_t)c * CAP + p] = r;
    }
}

// k2: fused dinv + fp16 payload (proven R16)
__global__ void k_hs16(const float* __restrict__ h) {
    int idx = blockIdx.x * blockDim.x + threadIdx.x;
    if (idx >= N_NODES * 32) return;
    int node = idx >> 5;
    float dn = rsqrtf((float)(__ldg(g_cur + node) + 1));
    if ((idx & 31) == 0) g_dinv[node] = dn;
    float4 v = __ldg((const float4*)h + idx);
    __half2 a = __floats2half2_rn(v.x * dn, v.y * dn);
    __half2 b = __floats2half2_rn(v.z * dn, v.w * dn);
    uint2 o;
    o.x = *(const uint32_t*)&a;
    o.y = *(const uint32_t*)&b;
    g_hs16[idx] = o;
}

// ---------------------------------------------------------------------------
// k3: gather (warp per node; proven R15/R16): fp16 payload, fp32 accumulation
// ---------------------------------------------------------------------------
__global__ void __launch_bounds__(256) k_gather() {
    int node = (blockIdx.x * blockDim.x + threadIdx.x) >> 5;
    if (node >= N_NODES) return;
    int tx = threadIdx.x & 31;

    uint2 s = __ldg(g_hs16 + (size_t)node * 32 + tx);
    float2 s0 = __half22float2(*(const __half2*)&s.x);
    float2 s1 = __half22float2(*(const __half2*)&s.y);
    float4 acc = make_float4(s0.x, s0.y, s1.x, s1.y);

    int cnt = __ldg(g_cur + node);
    if (cnt > CAP) cnt = CAP;
    const int* src = g_src + (size_t)node * CAP;
    int p = 0;
    for (; p + 4 <= cnt; p += 4) {
        int4 rr = __ldg((const int4*)(src + p));
        uint2 v0 = __ldg(g_hs16 + (size_t)rr.x * 32 + tx);
        uint2 v1 = __ldg(g_hs16 + (size_t)rr.y * 32 + tx);
        uint2 v2 = __ldg(g_hs16 + (size_t)rr.z * 32 + tx);
        uint2 v3 = __ldg(g_hs16 + (size_t)rr.w * 32 + tx);
        float2 a0 = __half22float2(*(const __half2*)&v0.x);
        float2 b0 = __half22float2(*(const __half2*)&v0.y);
        float2 a1 = __half22float2(*(const __half2*)&v1.x);
        float2 b1 = __half22float2(*(const __half2*)&v1.y);
        float2 a2 = __half22float2(*(const __half2*)&v2.x);
        float2 b2 = __half22float2(*(const __half2*)&v2.y);
        float2 a3 = __half22float2(*(const __half2*)&v3.x);
        float2 b3 = __half22float2(*(const __half2*)&v3.y);
        acc.x += a0.x + a1.x + a2.x + a3.x;
        acc.y += a0.y + a1.y + a2.y + a3.y;
        acc.z += b0.x + b1.x + b2.x + b3.x;
        acc.w += b0.y + b1.y + b2.y + b3.y;
    }
    for (; p < cnt; p++) {
        int r = __ldg(src + p);
        uint2 v = __ldg(g_hs16 + (size_t)r * 32 + tx);
        float2 a = __half22float2(*(const __half2*)&v.x);
        float2 b = __half22float2(*(const __half2*)&v.y);
        acc.x += a.x; acc.y += a.y; acc.z += b.x; acc.w += b.y;
    }
    float dn = __ldg(g_dinv + node);
    acc.x *= dn; acc.y *= dn; acc.z *= dn; acc.w *= dn;
    ((float4*)g_agg)[(size_t)node * 32 + tx] = acc;
}

// ---------------------------------------------------------------------------
// k4: HFMA2 MLP. k-pairs in half2 lanes (even/odd k chains); fp16 accumulators
//     flushed to fp32 every 16 pair-steps. Weight loads: 1 LDG.128 per kp.
//     Thread (tx,ty): 8 nodes x 4 hid cols (p1), 8 nodes x 2 out cols (p2).
// ---------------------------------------------------------------------------
__global__ void __launch_bounds__(256) k_mlp(const float* __restrict__ bg,
                                             const float* __restrict__ bf,
                                             float* __restrict__ out) {
    __shared__ char smraw[32768];
    __half2* sA16 = (__half2*)smraw;             // [node][kp], stride 64 (16 KB)
    __half2* sH16 = (__half2*)(smraw + 16384);   // hidden tile, same layout (16 KB)

    int tid = threadIdx.x;
    int tx = tid & 31;
    int ty = tid >> 5;
    int node0 = blockIdx.x * 64;

    // load agg tile -> half2-packed smem (pairs over k)
    for (int i = tid; i < 64 * 32; i += 256) {
        int node = node0 + (i >> 5);
        int q = i & 31;
        float4 v = make_float4(0.f, 0.f, 0.f, 0.f);
        if (node < N_NODES) v = __ldg((const float4*)g_agg + (size_t)node * 32 + q);
        __half2 p0 = __floats2half2_rn(v.x, v.y);
        __half2 p1 = __floats2half2_rn(v.z, v.w);
        uint2 o;
        o.x = *(const uint32_t*)&p0;
        o.y = *(const uint32_t*)&p1;
        *(uint2*)&sA16[(i >> 5) * 64 + 2 * q] = o;
    }
    __syncthreads();

    // ---- phase 1: hid = A @ Wg + bg  (fp16 MAC, fp32 chunk accumulation) ----
    float acc[8][4];
    {
        float4 b = __ldg((const float4*)bg + tx);
        #pragma unroll
        for (int i = 0; i < 8; i++) {
            acc[i][0] = b.x; acc[i][1] = b.y; acc[i][2] = b.z; acc[i][3] = b.w;
        }
    }
    const __half2 hz = __floats2half2_rn(0.f, 0.f);
    #pragma unroll
    for (int chunk = 0; chunk < 4; chunk++) {
        __half2 hacc[8][4];
        #pragma unroll
        for (int i = 0; i < 8; i++)
            #pragma unroll
            for (int j = 0; j < 4; j++) hacc[i][j] = hz;
        #pragma unroll 8
        for (int kk = 0; kk < 16; kk++) {
            int kp = chunk * 16 + kk;
            uint4 wr = __ldg((const uint4*)(g_Wgh + kp * 128) + tx);  // cols 4tx..4tx+3
            __half2 w0 = *(const __half2*)&wr.x;
            __half2 w1 = *(const __half2*)&wr.y;
            __half2 w2 = *(const __half2*)&wr.z;
            __half2 w3 = *(const __half2*)&wr.w;
            #pragma unroll
            for (int i = 0; i < 8; i++) {
                __half2 a = sA16[(8 * ty + i) * 64 + kp];   // broadcast
                hacc[i][0] = __hfma2(a, w0, hacc[i][0]);
                hacc[i][1] = __hfma2(a, w1, hacc[i][1]);
                hacc[i][2] = __hfma2(a, w2, hacc[i][2]);
                hacc[i][3] = __hfma2(a, w3, hacc[i][3]);
            }
        }
        #pragma unroll
        for (int i = 0; i < 8; i++)
            #pragma unroll
            for (int j = 0; j < 4; j++) {
                float2 f = __half22float2(hacc[i][j]);
                acc[i][j] += f.x + f.y;
            }
    }

    // relu -> hidden tile (cols 4tx..4tx+3 == pairs kp=2tx, 2tx+1); separate
    // smem region, so only one sync (before phase-2 reads) is needed.
    #pragma unroll
    for (int i = 0; i < 8; i++) {
        __half2 p0 = __floats2half2_rn(fmaxf(acc[i][0], 0.f), fmaxf(acc[i][1], 0.f));
        __half2 p1 = __floats2half2_rn(fmaxf(acc[i][2], 0.f), fmaxf(acc[i][3], 0.f));
        uint2 o;
        o.x = *(const uint32_t*)&p0;
        o.y = *(const uint32_t*)&p1;
        *(uint2*)&sH16[(8 * ty + i) * 64 + 2 * tx] = o;
    }
    __syncthreads();

    // ---- phase 2: out = hid @ Wf + bf ----
    float o32[8][2];
    {
        float2 b = __ldg((const float2*)bf + tx);
        #pragma unroll
        for (int i = 0; i < 8; i++) { o32[i][0] = b.x; o32[i][1] = b.y; }
    }
    #pragma unroll
    for (int chunk = 0; chunk < 4; chunk++) {
        __half2 ho[8][2];
        #pragma unroll
        for (int i = 0; i < 8; i++) { ho[i][0] = hz; ho[i][1] = hz; }
        #pragma unroll 8
        for (int kk = 0; kk < 16; kk++) {
            int kp = chunk * 16 + kk;
            uint2 wr = __ldg((const uint2*)(g_Wfh + kp * 64) + tx);   // cols 2tx, 2tx+1
            __half2 w0 = *(const __half2*)&wr.x;
            __half2 w1 = *(const __half2*)&wr.y;
            #pragma unroll
            for (int i = 0; i < 8; i++) {
                __half2 a = sH16[(8 * ty + i) * 64 + kp];
                ho[i][0] = __hfma2(a, w0, ho[i][0]);
                ho[i][1] = __hfma2(a, w1, ho[i][1]);
            }
        }
        #pragma unroll
        for (int i = 0; i < 8; i++) {
            float2 f0 = __half22float2(ho[i][0]);
            float2 f1 = __half22float2(ho[i][1]);
            o32[i][0] += f0.x + f0.y;
            o32[i][1] += f1.x + f1.y;
        }
    }

    #pragma unroll
    for (int i = 0; i < 8; i++) {
        int node = node0 + 8 * ty + i;
        if (node < N_NODES) {
            float2 v; v.x = o32[i][0]; v.y = o32[i][1];
            ((float2*)out)[(size_t)node * 32 + tx] = v;
        }
    }
}

// ---------------------------------------------------------------------------
// launch — inputs: h[f32 N*128], edge_index[2*E int32-or-int64],
//          W_gcn[f32 128*128], b_gcn[f32 128], W_fc[f32 128*64], b_fc[f32 64]
// output: f32 N*64
// ---------------------------------------------------------------------------
extern "C" void kernel_launch(void* const* d_in, const int* in_sizes, int n_in,
                              void* d_out, int out_size) {
    const float* h  = (const float*)d_in[0];
    const void*  ei = d_in[1];
    const float* Wg = (const float*)d_in[2];
    const float* bg = (const float*)d_in[3];
    const float* Wf = (const float*)d_in[4];
    const float* bf = (const float*)d_in[5];
    float* out = (float*)d_out;

    k_init  <<<(N_NODES + 255) / 256, 256>>>(ei, Wg, Wf);
    k_fill  <<<(N_EDGES + 255) / 256, 256>>>(ei);
    k_hs16  <<<(N_NODES * 32 + 255) / 256, 256>>>(h);   // fused dinv + fp16 payload
    k_gather<<<(N_NODES * 32 + 255) / 256, 256>>>();    // warp per node
    k_mlp   <<<(N_NODES + 63) / 64, 256>>>(bg, bf, out);
}